// round 12
// baseline (speedup 1.0000x reference)
#include <cuda_runtime.h>
#include <cuda_fp16.h>
#include <cstdint>

#define B_ 32
#define C_ 4
#define H_ 512
#define W_ 512
#define T_ 64
#define NPART 64
#define PITCH 514
// conflict-free smem swizzle
#define SW(i) ((i) ^ (((i) >> 3) & 15))

// ======= packed complex: one 64-bit reg = (re, im) as f32x2 =======
typedef unsigned long long cplx;

__device__ __forceinline__ cplx cpack(float re, float im){
    cplx r; asm("mov.b64 %0, {%1, %2};" : "=l"(r) : "f"(re), "f"(im)); return r;
}
__device__ __forceinline__ void cunpack(cplx a, float& re, float& im){
    asm("mov.b64 {%0, %1}, %2;" : "=f"(re), "=f"(im) : "l"(a));
}
__device__ __forceinline__ cplx cswap(cplx a){
    float re, im; cunpack(a, re, im); return cpack(im, re);
}
__device__ __forceinline__ cplx cadd(cplx a, cplx b){
    cplx r; asm("add.rn.f32x2 %0, %1, %2;" : "=l"(r) : "l"(a), "l"(b)); return r;
}
__device__ __forceinline__ cplx csub(cplx a, cplx b){
    cplx r; asm("sub.rn.f32x2 %0, %1, %2;" : "=l"(r) : "l"(a), "l"(b)); return r;
}
__device__ __forceinline__ cplx cmulc(cplx a, cplx b){      // elementwise
    cplx r; asm("mul.rn.f32x2 %0, %1, %2;" : "=l"(r) : "l"(a), "l"(b)); return r;
}
__device__ __forceinline__ cplx cfmac(cplx a, cplx b, cplx c){ // elementwise a*b+c
    cplx r; asm("fma.rn.f32x2 %0, %1, %2, %3;" : "=l"(r) : "l"(a), "l"(b), "l"(c)); return r;
}

// ------- packed radix kernels -------
template<int SGN> __device__ __forceinline__
void dft4p(cplx x0, cplx x1, cplx x2, cplx x3, cplx* y){
    cplx t0 = cadd(x0, x2), t1 = csub(x0, x2);
    cplx t2 = cadd(x1, x3), t3 = csub(x1, x3);
    y[0] = cadd(t0, t2);  y[2] = csub(t0, t2);
    const float s = (SGN > 0) ? 1.f : -1.f;
    cplx st3 = cswap(t3);
    y[1] = cfmac(st3, cpack(-s,  s), t1);   // t1 + sgn*j*t3
    y[3] = cfmac(st3, cpack( s, -s), t1);   // t1 - sgn*j*t3
}

template<int SGN> __device__ __forceinline__
void dft8p(const cplx* a, cplx* b){
    cplx E[4], O[4];
    dft4p<SGN>(a[0], a[2], a[4], a[6], E);
    dft4p<SGN>(a[1], a[3], a[5], a[7], O);
    const float c  = 0.70710678118654752440f;
    const float sc = (SGN > 0) ? c : -c;
    const float s  = (SGN > 0) ? 1.f : -1.f;
    cplx o1  = cfmac(cswap(O[1]), cpack(-sc, sc), cmulc(O[1], cpack( c,  c)));
    cplx o3  = cfmac(cswap(O[3]), cpack(-sc, sc), cmulc(O[3], cpack(-c, -c)));
    cplx so2 = cswap(O[2]);
    b[0] = cadd(E[0], O[0]);  b[4] = csub(E[0], O[0]);
    b[1] = cadd(E[1], o1);    b[5] = csub(E[1], o1);
    b[2] = cfmac(so2, cpack(-s,  s), E[2]);
    b[6] = cfmac(so2, cpack( s, -s), E[2]);
    b[3] = cadd(E[3], o3);    b[7] = csub(E[3], o3);
}

// ======= paired fp16 smem slot: {half2 itemA, half2 itemB} = 8B =======
__device__ __forceinline__ unsigned h2u(__half2 h){ return *reinterpret_cast<unsigned*>(&h); }

__device__ __forceinline__ uint2 pack2(cplx a, cplx b){
    float ar, ai, br, bi;
    cunpack(a, ar, ai); cunpack(b, br, bi);
    uint2 r;
    r.x = h2u(__floats2half2_rn(ar, ai));
    r.y = h2u(__floats2half2_rn(br, bi));
    return r;
}
__device__ __forceinline__ void unpack2(uint2 v, cplx& a, cplx& b){
    __half2 ha = *reinterpret_cast<__half2*>(&v.x);
    __half2 hb = *reinterpret_cast<__half2*>(&v.y);
    float2 fa = __half22float2(ha), fb = __half22float2(hb);
    a = cpack(fa.x, fa.y); b = cpack(fb.x, fb.y);
}

// twiddle+store for a PAIR (shared twiddle chain, packed fp16 store)
__device__ __forceinline__
void twiddle_store2(uint2* A, const cplx* b0, const cplx* b1, float wx, float wy, int idx0, int step){
    A[SW(idx0)] = pack2(b0[0], b1[0]);
    cplx cwx = cpack(wx, wx);
    cplx cwy = cpack(-wy, wy);
    #pragma unroll
    for(int k = 1; k < 8; k++){
        cplx t0 = cfmac(cwy, cswap(b0[k]), cmulc(cwx, b0[k]));
        cplx t1 = cfmac(cwy, cswap(b1[k]), cmulc(cwx, b1[k]));
        A[SW(idx0 + step*k)] = pack2(t0, t1);
        if(k < 7){
            cplx nx = cfmac(cwy, cpack( wy, -wy), cmulc(cwx, cpack(wx, wx)));
            cplx ny = cfmac(cwy, cpack( wx,  wx), cmulc(cwx, cpack(-wy, wy)));
            cwx = nx; cwy = ny;
        }
    }
}

// scaled variant: stores scale * (b[k] * w^k); chain carries the scale for free
__device__ __forceinline__
void twiddle_store2s(uint2* A, const cplx* b0, const cplx* b1, float wx, float wy,
                     int idx0, int step, float scale){
    cplx cs = cpack(scale, scale);
    A[SW(idx0)] = pack2(cmulc(b0[0], cs), cmulc(b1[0], cs));
    cplx cwx = cpack(scale*wx, scale*wx);
    cplx cwy = cpack(-scale*wy, scale*wy);
    #pragma unroll
    for(int k = 1; k < 8; k++){
        cplx t0 = cfmac(cwy, cswap(b0[k]), cmulc(cwx, b0[k]));
        cplx t1 = cfmac(cwy, cswap(b1[k]), cmulc(cwx, b1[k]));
        A[SW(idx0 + step*k)] = pack2(t0, t1);
        if(k < 7){   // recurrence coefficients UNSCALED -> chain keeps scale·w^k
            cplx nx = cfmac(cwy, cpack( wy, -wy), cmulc(cwx, cpack(wx, wx)));
            cplx ny = cfmac(cwy, cpack( wx,  wx), cmulc(cwx, cpack(-wy, wy)));
            cwx = nx; cwy = ny;
        }
    }
}

// ------- scratch (static device globals; no allocation) -------
__device__ float   g_part[B_ * 2 * NPART * W_];
__device__ int     g_sel [B_ * 2 * T_];          // selected cols per (b,g), SORTED by j
__device__ __half2 g_Yh  [B_ * C_ * H_ * T_];    // ifft_H result (fp16), (bc, k, t)
__device__ float2  g_tw  [512];                  // e^{-2pi i n/512}

__device__ __forceinline__ void load_tw(float2* tw64, float2* tw8, int tid){
    if(tid < 64) tw64[tid] = g_tw[tid];
    if(tid < 8)  tw8[tid]  = g_tw[8*tid];
}

// ------- kernel 1: diff partials (+ twiddle init in block 0) -------
__global__ void k_diff(const float* __restrict__ xr, const float* __restrict__ xi){
    int blk = blockIdx.x;                 // bg*16 + ch, 1024 blocks
    if(blk == 0){
        int n = threadIdx.x;
        float s, c;
        sincospif((float)n * (1.0f/256.0f), &s, &c);
        g_tw[n] = make_float2(c, -s);
    }
    int ch  = blk & 15;
    int bg  = blk >> 4;
    int b   = bg >> 1, g = bg & 1;
    int tid = threadIdx.x;
    int tq  = tid & 127;
    int sub = tid >> 7;                   // 0..3 -> 8 rows each
    const float4* xr4 = (const float4*)xr;
    const float4* xi4 = (const float4*)xi;
    size_t base0 = (size_t)(b*4 + 2*g    ) * H_ * (W_/4);
    size_t base1 = (size_t)(b*4 + 2*g + 1) * H_ * (W_/4);
    int h0 = ch * 32 + sub * 8;
    float4 acc = make_float4(0.f, 0.f, 0.f, 0.f);
    #pragma unroll
    for(int h = h0; h < h0 + 8; h++){
        float4 r0 = xr4[base0 + (size_t)h*(W_/4) + tq];
        float4 i0 = xi4[base0 + (size_t)h*(W_/4) + tq];
        float4 r1 = xr4[base1 + (size_t)h*(W_/4) + tq];
        float4 i1 = xi4[base1 + (size_t)h*(W_/4) + tq];
        acc.x += fabsf(fabsf(r0.x) - fabsf(i1.x)) + fabsf(fabsf(r1.x) - fabsf(i0.x));
        acc.y += fabsf(fabsf(r0.y) - fabsf(i1.y)) + fabsf(fabsf(r1.y) - fabsf(i0.y));
        acc.z += fabsf(fabsf(r0.z) - fabsf(i1.z)) + fabsf(fabsf(r1.z) - fabsf(i0.z));
        acc.w += fabsf(fabsf(r0.w) - fabsf(i1.w)) + fabsf(fabsf(r1.w) - fabsf(i0.w));
    }
    ((float4*)g_part)[((size_t)bg * NPART + ch*4 + sub) * 128 + tq] = acc;
}

// ------- kernel 2: exact stable top-64, output SORTED by column index -------
__global__ void k_select(){
    __shared__ float d[W_];
    __shared__ unsigned selw[16];
    int bg = blockIdx.x;                  // 64 blocks
    int w  = threadIdx.x;
    float s = 0.f;
    #pragma unroll 8
    for(int p = 0; p < NPART; p++)
        s += g_part[((size_t)bg * NPART + p) * W_ + w];
    d[w] = s;
    __syncthreads();
    int rank = 0;
    const float4* d4 = (const float4*)d;
    #pragma unroll 4
    for(int j4 = 0; j4 < 128; j4++){
        float4 v = d4[j4];
        int j = 4*j4;
        rank += (v.x < s) || (v.x == s && j   < w);
        rank += (v.y < s) || (v.y == s && j+1 < w);
        rank += (v.z < s) || (v.z == s && j+2 < w);
        rank += (v.w < s) || (v.w == s && j+3 < w);
    }
    bool sel = rank < T_;
    unsigned m = __ballot_sync(0xffffffffu, sel);
    int wid = w >> 5, lane = w & 31;
    if(lane == 0) selw[wid] = m;
    __syncthreads();
    if(sel){
        int pos = __popc(m & ((1u << lane) - 1u));
        #pragma unroll
        for(int k = 0; k < 16; k++) if(k < wid) pos += __popc(selw[k]);
        g_sel[bg * T_ + pos] = w;         // ascending j
    }
}

// ------- kernel 3: FUSED gather + PAIRED ifft_H + direct packed Y write -------
__global__ void __launch_bounds__(256, 4) k_colfft(const float* __restrict__ xr, const float* __restrict__ xi){
    __shared__ __align__(16) uint2 A[4][PITCH];   // slot = {col 2cp, col 2cp+1} fp16
    __shared__ float2 tw64[64];
    __shared__ float2 tw8[8];
    __shared__ int jcol[8];
    int tid = threadIdx.x;                // 256 threads
    load_tw(tw64, tw8, tid);
    int blk = blockIdx.x;                 // bc*8 + tg, 1024 blocks
    int bc  = blk >> 3;
    int tg  = blk & 7;
    int b = bc >> 2, c = bc & 3, g = c >> 1;
    if(tid < 8) jcol[tid] = g_sel[(b*2 + g) * T_ + tg*8 + tid];
    __syncthreads();
    // gather: lane group covers 8 sorted-adjacent columns per row (sector dedup)
    int c2 = tid & 3, hb = tid >> 2;      // column-pair, h-base 0..63
    int j0 = jcol[2*c2], j1 = jcol[2*c2 + 1];
    size_t rowbase = (size_t)bc * H_ * W_;
    #pragma unroll
    for(int p = 0; p < 8; p++){
        int h = hb + 64*p;
        size_t off = rowbase + (size_t)h * W_;
        uint2 pk;
        pk.x = h2u(__floats2half2_rn(xr[off + j0], xi[off + j0]));
        pk.y = h2u(__floats2half2_rn(xr[off + j1], xi[off + j1]));
        A[c2][SW(h)] = pk;
    }
    __syncthreads();
    int f2 = tid >> 6, u = tid & 63;      // f2 = column-pair for FFT phase
    cplx a0[8], a1[8], b0[8], b1[8];
    // stage 1 (inverse; 1/512 scale folded into twiddle chain)
    #pragma unroll
    for(int q = 0; q < 8; q++) unpack2(A[f2][SW(u + 64*q)], a0[q], a1[q]);
    dft8p<+1>(a0, b0);
    dft8p<+1>(a1, b1);
    float2 w1 = tw64[u];
    twiddle_store2s(A[f2], b0, b1, w1.x, -w1.y, u, 64, 1.0f/512.0f);
    __syncthreads();
    // stage 2
    int k0 = u >> 3, n2 = u & 7;
    int base = 64*k0;
    #pragma unroll
    for(int p = 0; p < 8; p++) unpack2(A[f2][SW(base + n2 + 8*p)], a0[p], a1[p]);
    dft8p<+1>(a0, b0);
    dft8p<+1>(a1, b1);
    float2 w2 = tw8[n2];
    twiddle_store2(A[f2], b0, b1, w2.x, -w2.y, base + n2, 8);
    __syncthreads();
    // stage 3, digit-reversed packed store back to smem
    int k1 = u & 7;
    #pragma unroll
    for(int n = 0; n < 8; n++) unpack2(A[f2][SW(n + 8*k1 + 64*k0)], a0[n], a1[n]);
    dft8p<+1>(a0, b0);
    dft8p<+1>(a1, b1);
    __syncthreads();
    #pragma unroll
    for(int k2 = 0; k2 < 8; k2++) A[f2][SW(k0 + 8*k1 + 64*k2)] = pack2(b0[k2], b1[k2]);
    __syncthreads();
    // copy-out: slot already IS the packed (t0,t1) pair Y wants
    uint2* Y2 = (uint2*)g_Yh;
    int tp = tid & 3, kb = tid >> 2;
    #pragma unroll
    for(int p = 0; p < 8; p++){
        int kk = kb + 64*p;
        Y2[((size_t)bc * H_ + kk) * (T_/2) + tg*4 + tp] = A[tp][SW(kk)];
    }
}

// ------- kernel 4: PAIRED scatter + fft_W + 0.5 (2 rows per smem slot, fp16) -------
__global__ void __launch_bounds__(256, 4) k_rowfft(float2* __restrict__ out){
    __shared__ __align__(16) uint2 A[4][PITCH];   // slot = {half2 row0, half2 row1}
    __shared__ float2 tw64[64];
    __shared__ float2 tw8[8];
    __shared__ int jj[T_];
    int tid = threadIdx.x;                // 256 threads
    load_tw(tw64, tw8, tid);
    int blk = blockIdx.x;                 // bc*64 + hg, 8192 blocks
    int bc  = blk >> 6;
    int hg  = blk & 63;
    int b = bc >> 2, c = bc & 3, g = c >> 1;
    if(tid < T_) jj[tid] = g_sel[(b*2 + g) * T_ + tid];
    int f2 = tid >> 6, u = tid & 63;
    int h0 = hg * 8 + 2*f2, h1 = h0 + 1;
    // zero all 512 slots of this pair-row
    uint4* Az = (uint4*)(&A[f2][0]);
    #pragma unroll
    for(int q = 0; q < 4; q++) Az[u + 64*q] = make_uint4(0,0,0,0);
    __syncthreads();
    // scatter both rows' value t=u into slot jj[u] (no cvt: already fp16)
    {
        const __half2* Y0 = g_Yh + ((size_t)bc * H_ + h0) * T_;
        const __half2* Y1 = g_Yh + ((size_t)bc * H_ + h1) * T_;
        __half2 v0 = Y0[u], v1 = Y1[u];
        uint2 pk; pk.x = h2u(v0); pk.y = h2u(v1);
        A[f2][SW(jj[u])] = pk;
    }
    __syncthreads();
    // stages 1+2 on the pair
    cplx a0[8], a1[8], b0[8], b1[8];
    {
        #pragma unroll
        for(int q = 0; q < 8; q++) unpack2(A[f2][SW(u + 64*q)], a0[q], a1[q]);
        dft8p<-1>(a0, b0);
        dft8p<-1>(a1, b1);
        float2 w1 = tw64[u];
        twiddle_store2(A[f2], b0, b1, w1.x, w1.y, u, 64);
    }
    __syncthreads();
    int k0 = u >> 3, n2 = u & 7;
    int base = 64*k0;
    {
        #pragma unroll
        for(int p = 0; p < 8; p++) unpack2(A[f2][SW(base + n2 + 8*p)], a0[p], a1[p]);
        dft8p<-1>(a0, b0);
        dft8p<-1>(a1, b1);
        float2 w2 = tw8[n2];
        twiddle_store2(A[f2], b0, b1, w2.x, w2.y, base + n2, 8);
    }
    __syncthreads();
    // stage 3 in registers, direct global stores for both rows
    int k1 = u & 7;
    #pragma unroll
    for(int n = 0; n < 8; n++) unpack2(A[f2][SW(n + 8*k1 + 64*k0)], a0[n], a1[n]);
    dft8p<-1>(a0, b0);
    dft8p<-1>(a1, b1);
    const cplx CHALF = cpack(0.5f, 0.f);
    cplx* o0 = reinterpret_cast<cplx*>(out) + ((size_t)bc * H_ + h0) * W_ + (k0 + 8*k1);
    cplx* o1 = reinterpret_cast<cplx*>(out) + ((size_t)bc * H_ + h1) * W_ + (k0 + 8*k1);
    #pragma unroll
    for(int k2 = 0; k2 < 8; k2++){
        o0[64*k2] = cadd(b0[k2], CHALF);
        o1[64*k2] = cadd(b1[k2], CHALF);
    }
}

extern "C" void kernel_launch(void* const* d_in, const int* in_sizes, int n_in,
                              void* d_out, int out_size){
    const float* xr = (const float*)d_in[0];
    const float* xi = (const float*)d_in[1];
    float2* out = (float2*)d_out;

    k_diff   <<<B_ * 2 * 16, 512>>>(xr, xi);
    k_select <<<B_ * 2, 512>>>();
    k_colfft <<<B_ * C_ * 8, 256>>>(xr, xi);
    k_rowfft <<<B_ * C_ * H_ / 8, 256>>>(out);
}

// round 13
// speedup vs baseline: 1.0267x; 1.0267x over previous
#include <cuda_runtime.h>
#include <cuda_fp16.h>
#include <cstdint>

#define B_ 32
#define C_ 4
#define H_ 512
#define W_ 512
#define T_ 64
#define NPART 64
#define PITCH 514
// conflict-free smem swizzle
#define SW(i) ((i) ^ (((i) >> 3) & 15))

// ======= packed complex: one 64-bit reg = (re, im) as f32x2 =======
typedef unsigned long long cplx;

__device__ __forceinline__ cplx cpack(float re, float im){
    cplx r; asm("mov.b64 %0, {%1, %2};" : "=l"(r) : "f"(re), "f"(im)); return r;
}
__device__ __forceinline__ void cunpack(cplx a, float& re, float& im){
    asm("mov.b64 {%0, %1}, %2;" : "=f"(re), "=f"(im) : "l"(a));
}
__device__ __forceinline__ cplx cswap(cplx a){
    float re, im; cunpack(a, re, im); return cpack(im, re);
}
__device__ __forceinline__ cplx cadd(cplx a, cplx b){
    cplx r; asm("add.rn.f32x2 %0, %1, %2;" : "=l"(r) : "l"(a), "l"(b)); return r;
}
__device__ __forceinline__ cplx csub(cplx a, cplx b){
    cplx r; asm("sub.rn.f32x2 %0, %1, %2;" : "=l"(r) : "l"(a), "l"(b)); return r;
}
__device__ __forceinline__ cplx cmulc(cplx a, cplx b){      // elementwise
    cplx r; asm("mul.rn.f32x2 %0, %1, %2;" : "=l"(r) : "l"(a), "l"(b)); return r;
}
__device__ __forceinline__ cplx cfmac(cplx a, cplx b, cplx c){ // elementwise a*b+c
    cplx r; asm("fma.rn.f32x2 %0, %1, %2, %3;" : "=l"(r) : "l"(a), "l"(b), "l"(c)); return r;
}

// ------- packed radix kernels -------
template<int SGN> __device__ __forceinline__
void dft4p(cplx x0, cplx x1, cplx x2, cplx x3, cplx* y){
    cplx t0 = cadd(x0, x2), t1 = csub(x0, x2);
    cplx t2 = cadd(x1, x3), t3 = csub(x1, x3);
    y[0] = cadd(t0, t2);  y[2] = csub(t0, t2);
    const float s = (SGN > 0) ? 1.f : -1.f;
    cplx st3 = cswap(t3);
    y[1] = cfmac(st3, cpack(-s,  s), t1);   // t1 + sgn*j*t3
    y[3] = cfmac(st3, cpack( s, -s), t1);   // t1 - sgn*j*t3
}

template<int SGN> __device__ __forceinline__
void dft8p(const cplx* a, cplx* b){
    cplx E[4], O[4];
    dft4p<SGN>(a[0], a[2], a[4], a[6], E);
    dft4p<SGN>(a[1], a[3], a[5], a[7], O);
    const float c  = 0.70710678118654752440f;
    const float sc = (SGN > 0) ? c : -c;
    const float s  = (SGN > 0) ? 1.f : -1.f;
    cplx o1  = cfmac(cswap(O[1]), cpack(-sc, sc), cmulc(O[1], cpack( c,  c)));
    cplx o3  = cfmac(cswap(O[3]), cpack(-sc, sc), cmulc(O[3], cpack(-c, -c)));
    cplx so2 = cswap(O[2]);
    b[0] = cadd(E[0], O[0]);  b[4] = csub(E[0], O[0]);
    b[1] = cadd(E[1], o1);    b[5] = csub(E[1], o1);
    b[2] = cfmac(so2, cpack(-s,  s), E[2]);
    b[6] = cfmac(so2, cpack( s, -s), E[2]);
    b[3] = cadd(E[3], o3);    b[7] = csub(E[3], o3);
}

// apply twiddle powers w^k (k=0..7) to b[k] and store; splat-form chain. (fp32 smem)
__device__ __forceinline__
void twiddle_store(cplx* A, const cplx* b, float wx, float wy, int idx0, int step){
    A[SW(idx0)] = b[0];
    cplx cwx = cpack(wx, wx);
    cplx cwy = cpack(-wy, wy);
    #pragma unroll
    for(int k = 1; k < 8; k++){
        A[SW(idx0 + step*k)] = cfmac(cwy, cswap(b[k]), cmulc(cwx, b[k]));
        if(k < 7){
            cplx nx = cfmac(cwy, cpack( wy, -wy), cmulc(cwx, cpack(wx, wx)));
            cplx ny = cfmac(cwy, cpack( wx,  wx), cmulc(cwx, cpack(-wy, wy)));
            cwx = nx; cwy = ny;
        }
    }
}

// ======= paired fp16 smem slot: {half2 rowA, half2 rowB} = 8B =======
__device__ __forceinline__ unsigned h2u(__half2 h){ return *reinterpret_cast<unsigned*>(&h); }

__device__ __forceinline__ uint2 pack2(cplx a, cplx b){
    float ar, ai, br, bi;
    cunpack(a, ar, ai); cunpack(b, br, bi);
    uint2 r;
    r.x = h2u(__floats2half2_rn(ar, ai));
    r.y = h2u(__floats2half2_rn(br, bi));
    return r;
}
__device__ __forceinline__ void unpack2(uint2 v, cplx& a, cplx& b){
    __half2 ha = *reinterpret_cast<__half2*>(&v.x);
    __half2 hb = *reinterpret_cast<__half2*>(&v.y);
    float2 fa = __half22float2(ha), fb = __half22float2(hb);
    a = cpack(fa.x, fa.y); b = cpack(fb.x, fb.y);
}

// twiddle+store for a PAIR (shared twiddle chain, packed fp16 store)
__device__ __forceinline__
void twiddle_store2(uint2* A, const cplx* b0, const cplx* b1, float wx, float wy, int idx0, int step){
    A[SW(idx0)] = pack2(b0[0], b1[0]);
    cplx cwx = cpack(wx, wx);
    cplx cwy = cpack(-wy, wy);
    #pragma unroll
    for(int k = 1; k < 8; k++){
        cplx t0 = cfmac(cwy, cswap(b0[k]), cmulc(cwx, b0[k]));
        cplx t1 = cfmac(cwy, cswap(b1[k]), cmulc(cwx, b1[k]));
        A[SW(idx0 + step*k)] = pack2(t0, t1);
        if(k < 7){
            cplx nx = cfmac(cwy, cpack( wy, -wy), cmulc(cwx, cpack(wx, wx)));
            cplx ny = cfmac(cwy, cpack( wx,  wx), cmulc(cwx, cpack(-wy, wy)));
            cwx = nx; cwy = ny;
        }
    }
}

// ------- scratch (static device globals; no allocation) -------
__device__ float   g_part[B_ * 2 * NPART * W_];
__device__ int     g_sel [B_ * 2 * T_];          // selected cols per (b,g), SORTED by j
__device__ __half2 g_Yh  [B_ * C_ * H_ * T_];    // ifft_H result (fp16), (bc, k, t)
__device__ float2  g_tw  [512];                  // e^{-2pi i n/512}

__device__ __forceinline__ void load_tw(float2* tw64, float2* tw8, int tid){
    if(tid < 64) tw64[tid] = g_tw[tid];
    if(tid < 8)  tw8[tid]  = g_tw[8*tid];
}

// ------- kernel 1: diff partials (+ twiddle init in block 0) -------
__global__ void k_diff(const float* __restrict__ xr, const float* __restrict__ xi){
    int blk = blockIdx.x;                 // bg*16 + ch, 1024 blocks
    if(blk == 0){
        int n = threadIdx.x;
        float s, c;
        sincospif((float)n * (1.0f/256.0f), &s, &c);
        g_tw[n] = make_float2(c, -s);
    }
    int ch  = blk & 15;
    int bg  = blk >> 4;
    int b   = bg >> 1, g = bg & 1;
    int tid = threadIdx.x;
    int tq  = tid & 127;
    int sub = tid >> 7;                   // 0..3 -> 8 rows each
    const float4* xr4 = (const float4*)xr;
    const float4* xi4 = (const float4*)xi;
    size_t base0 = (size_t)(b*4 + 2*g    ) * H_ * (W_/4);
    size_t base1 = (size_t)(b*4 + 2*g + 1) * H_ * (W_/4);
    int h0 = ch * 32 + sub * 8;
    float4 acc = make_float4(0.f, 0.f, 0.f, 0.f);
    #pragma unroll
    for(int h = h0; h < h0 + 8; h++){
        float4 r0 = xr4[base0 + (size_t)h*(W_/4) + tq];
        float4 i0 = xi4[base0 + (size_t)h*(W_/4) + tq];
        float4 r1 = xr4[base1 + (size_t)h*(W_/4) + tq];
        float4 i1 = xi4[base1 + (size_t)h*(W_/4) + tq];
        acc.x += fabsf(fabsf(r0.x) - fabsf(i1.x)) + fabsf(fabsf(r1.x) - fabsf(i0.x));
        acc.y += fabsf(fabsf(r0.y) - fabsf(i1.y)) + fabsf(fabsf(r1.y) - fabsf(i0.y));
        acc.z += fabsf(fabsf(r0.z) - fabsf(i1.z)) + fabsf(fabsf(r1.z) - fabsf(i0.z));
        acc.w += fabsf(fabsf(r0.w) - fabsf(i1.w)) + fabsf(fabsf(r1.w) - fabsf(i0.w));
    }
    ((float4*)g_part)[((size_t)bg * NPART + ch*4 + sub) * 128 + tq] = acc;
}

// ------- kernel 2: exact stable top-64, output SORTED by column index -------
__global__ void k_select(){
    __shared__ float d[W_];
    __shared__ unsigned selw[16];
    int bg = blockIdx.x;                  // 64 blocks
    int w  = threadIdx.x;
    float s = 0.f;
    #pragma unroll 8
    for(int p = 0; p < NPART; p++)
        s += g_part[((size_t)bg * NPART + p) * W_ + w];
    d[w] = s;
    __syncthreads();
    int rank = 0;
    const float4* d4 = (const float4*)d;
    #pragma unroll 4
    for(int j4 = 0; j4 < 128; j4++){
        float4 v = d4[j4];
        int j = 4*j4;
        rank += (v.x < s) || (v.x == s && j   < w);
        rank += (v.y < s) || (v.y == s && j+1 < w);
        rank += (v.z < s) || (v.z == s && j+2 < w);
        rank += (v.w < s) || (v.w == s && j+3 < w);
    }
    bool sel = rank < T_;
    unsigned m = __ballot_sync(0xffffffffu, sel);
    int wid = w >> 5, lane = w & 31;
    if(lane == 0) selw[wid] = m;
    __syncthreads();
    if(sel){
        int pos = __popc(m & ((1u << lane) - 1u));
        #pragma unroll
        for(int k = 0; k < 16; k++) if(k < wid) pos += __popc(selw[k]);
        g_sel[bg * T_ + pos] = w;         // ascending j
    }
}

// ------- kernel 3: FUSED gather + ifft_H (fp32) + transposed fp16 Y write -------
__global__ void k_colfft(const float* __restrict__ xr, const float* __restrict__ xi){
    __shared__ __align__(16) cplx A[8][PITCH];
    __shared__ float2 tw64[64];
    __shared__ float2 tw8[8];
    __shared__ int jcol[8];
    int tid = threadIdx.x;
    load_tw(tw64, tw8, tid);
    int blk = blockIdx.x;                 // bc*8 + tg, 1024 blocks
    int bc  = blk >> 3;
    int tg  = blk & 7;
    int b = bc >> 2, c = bc & 3, g = c >> 1;
    if(tid < 8) jcol[tid] = g_sel[(b*2 + g) * T_ + tg*8 + tid];
    __syncthreads();
    // direct gather: warp = 4 rows x 8 sorted-adjacent columns
    int f2    = tid & 7;
    int hbase = tid >> 3;                 // 0..63
    int j     = jcol[f2];
    const float scale = 1.0f / 512.0f;    // ifft normalization
    size_t rowbase = (size_t)bc * H_ * W_;
    #pragma unroll
    for(int pass = 0; pass < 8; pass++){
        int h = hbase + 64*pass;
        size_t off = rowbase + (size_t)h * W_ + j;
        A[f2][SW(h)] = cpack(xr[off] * scale, xi[off] * scale);
    }
    __syncthreads();
    int f = tid >> 6, u = tid & 63;
    // stage 1
    cplx a[8], b2[8];
    #pragma unroll
    for(int q = 0; q < 8; q++) a[q] = A[f][SW(u + 64*q)];
    dft8p<+1>(a, b2);
    {
        float2 w1 = tw64[u];
        twiddle_store(A[f], b2, w1.x, -w1.y, u, 64);
    }
    __syncthreads();
    // stage 2
    int k0 = u >> 3, n2 = u & 7;
    int base = 64*k0;
    #pragma unroll
    for(int p = 0; p < 8; p++) a[p] = A[f][SW(base + n2 + 8*p)];
    dft8p<+1>(a, b2);
    {
        float2 w2 = tw8[n2];
        twiddle_store(A[f], b2, w2.x, -w2.y, base + n2, 8);
    }
    __syncthreads();
    // stage 3 + digit-reversed smem store (natural order)
    {
        int k1 = u & 7;
        #pragma unroll
        for(int n = 0; n < 8; n++) a[n] = A[f][SW(n + 8*k1 + 64*k0)];
        dft8p<+1>(a, b2);
        __syncthreads();
        #pragma unroll
        for(int k2 = 0; k2 < 8; k2++) A[f][SW(k0 + 8*k1 + 64*k2)] = b2[k2];
    }
    __syncthreads();
    // transposed fp16 write of Y (two adjacent t per 8B store)
    uint2* Y2 = (uint2*)g_Yh;
    int tp = tid & 3;
    #pragma unroll
    for(int pass = 0; pass < 4; pass++){
        int kk = (tid >> 2) + pass * 128;
        Y2[((size_t)bc * H_ + kk) * (T_/2) + tg*4 + tp] = pack2(A[2*tp][SW(kk)], A[2*tp + 1][SW(kk)]);
    }
}

// ------- kernel 4: PAIRED scatter + fft_W + 0.5 (2 rows per smem slot, fp16) -------
__global__ void __launch_bounds__(256, 5) k_rowfft(float2* __restrict__ out){
    __shared__ __align__(16) uint2 A[4][PITCH];   // slot = {half2 row0, half2 row1}
    __shared__ float2 tw64[64];
    __shared__ float2 tw8[8];
    __shared__ int jj[T_];
    int tid = threadIdx.x;                // 256 threads
    load_tw(tw64, tw8, tid);
    int blk = blockIdx.x;                 // bc*64 + hg, 8192 blocks
    int bc  = blk >> 6;
    int hg  = blk & 63;
    int b = bc >> 2, c = bc & 3, g = c >> 1;
    if(tid < T_) jj[tid] = g_sel[(b*2 + g) * T_ + tid];
    int f2 = tid >> 6, u = tid & 63;
    int h0 = hg * 8 + 2*f2, h1 = h0 + 1;
    // zero all 512 slots of this pair-row
    uint4* Az = (uint4*)(&A[f2][0]);
    #pragma unroll
    for(int q = 0; q < 4; q++) Az[u + 64*q] = make_uint4(0,0,0,0);
    __syncthreads();
    // scatter both rows' value t=u into slot jj[u] (no cvt: already fp16)
    {
        const __half2* Y0 = g_Yh + ((size_t)bc * H_ + h0) * T_;
        const __half2* Y1 = g_Yh + ((size_t)bc * H_ + h1) * T_;
        __half2 v0 = Y0[u], v1 = Y1[u];
        uint2 pk; pk.x = h2u(v0); pk.y = h2u(v1);
        A[f2][SW(jj[u])] = pk;
    }
    __syncthreads();
    // stages 1+2 on the pair
    cplx a0[8], a1[8], b0[8], b1[8];
    {
        #pragma unroll
        for(int q = 0; q < 8; q++) unpack2(A[f2][SW(u + 64*q)], a0[q], a1[q]);
        dft8p<-1>(a0, b0);
        dft8p<-1>(a1, b1);
        float2 w1 = tw64[u];
        twiddle_store2(A[f2], b0, b1, w1.x, w1.y, u, 64);
    }
    __syncthreads();
    int k0 = u >> 3, n2 = u & 7;
    int base = 64*k0;
    {
        #pragma unroll
        for(int p = 0; p < 8; p++) unpack2(A[f2][SW(base + n2 + 8*p)], a0[p], a1[p]);
        dft8p<-1>(a0, b0);
        dft8p<-1>(a1, b1);
        float2 w2 = tw8[n2];
        twiddle_store2(A[f2], b0, b1, w2.x, w2.y, base + n2, 8);
    }
    __syncthreads();
    // stage 3 in registers, direct global stores for both rows
    int k1 = u & 7;
    #pragma unroll
    for(int n = 0; n < 8; n++) unpack2(A[f2][SW(n + 8*k1 + 64*k0)], a0[n], a1[n]);
    dft8p<-1>(a0, b0);
    dft8p<-1>(a1, b1);
    const cplx CHALF = cpack(0.5f, 0.f);
    cplx* o0 = reinterpret_cast<cplx*>(out) + ((size_t)bc * H_ + h0) * W_ + (k0 + 8*k1);
    cplx* o1 = reinterpret_cast<cplx*>(out) + ((size_t)bc * H_ + h1) * W_ + (k0 + 8*k1);
    #pragma unroll
    for(int k2 = 0; k2 < 8; k2++){
        o0[64*k2] = cadd(b0[k2], CHALF);
        o1[64*k2] = cadd(b1[k2], CHALF);
    }
}

extern "C" void kernel_launch(void* const* d_in, const int* in_sizes, int n_in,
                              void* d_out, int out_size){
    const float* xr = (const float*)d_in[0];
    const float* xi = (const float*)d_in[1];
    float2* out = (float2*)d_out;

    k_diff   <<<B_ * 2 * 16, 512>>>(xr, xi);
    k_select <<<B_ * 2, 512>>>();
    k_colfft <<<B_ * C_ * 8, 512>>>(xr, xi);
    k_rowfft <<<B_ * C_ * H_ / 8, 256>>>(out);
}